// round 7
// baseline (speedup 1.0000x reference)
#include <cuda_runtime.h>

// Problem constants
#define Bc 64
#define Sc 2048
#define Dc 512
#define Uc 512
#define TSR 64     // rows per score block
#define KT  16     // K tile
#define NCH 8      // context S-chunks per batch

// Scratch (no allocations allowed)
__device__ float g_qp[Bc * Uc];        // q_proj + b1 + b2
__device__ float g_scores[Bc * Sc];    // raw scores
__device__ float g_max[Bc];
__device__ float g_rsum[Bc];
__device__ float g_part[Bc * NCH * Dc];

// compile-time unroller (constexpr index for "n" asm constraints)
template <int J> struct IC { static constexpr int v = J; };
template <int N, class F>
__device__ __forceinline__ void sfor(F&& f) {
    if constexpr (N > 0) { sfor<N - 1>(f); f(IC<N - 1>{}); }
}

// ---------------------------------------------------------------------------
// Kernel A: q_proj[b][u] = query[b]@W1[:,u] + b1[u] + b2[u]
// ---------------------------------------------------------------------------
__global__ void qproj_kernel(const float* __restrict__ query,
                             const float* __restrict__ W1,
                             const float* __restrict__ b1,
                             const float* __restrict__ b2) {
    __shared__ float q[Dc];
    const int b = blockIdx.x, t = threadIdx.x;
    q[t] = query[b * Dc + t];
    __syncthreads();
    float acc = b1[t] + b2[t];
#pragma unroll 8
    for (int d = 0; d < Dc; d++)
        acc = fmaf(q[d], W1[d * Uc + t], acc);
    g_qp[b * Uc + t] = acc;
}

// ---------------------------------------------------------------------------
// Kernel B: fused  scores[row] = V . tanh(q_proj[b] + values[row]@W2)
// Block: 64 rows x 512 cols, 512 threads, f32x2-packed accumulators.
// ---------------------------------------------------------------------------
__global__ void __launch_bounds__(512, 1)
score_kernel(const float* __restrict__ values,
             const float* __restrict__ W2,
             const float* __restrict__ Vw) {
    __shared__ float  W2s[KT][Uc];          // 32 KB: W2[k0+kk][c]
    __shared__ float4 Vs4[TSR / 2][KT / 2]; // 4 KB: {v(2j,k0),v(2j+1,k0),v(2j,k1),v(2j+1,k1)}
    __shared__ float  red[TSR][17];         // reduction scratch

    const int t = threadIdx.x;
    const int row0 = blockIdx.x * TSR;   // global row in [0, B*S)
    const int b = row0 >> 11;            // row0 / Sc (TSR divides Sc)

    unsigned long long acc[32];
#pragma unroll
    for (int j = 0; j < 32; j++) acc[j] = 0ULL;

    const unsigned vs_base = (unsigned)__cvta_generic_to_shared(Vs4);

    // values-tile loader mapping: thread -> (row lr, k-pair lkp), float2 per thread
    const int lr  = t >> 3;   // 0..63
    const int lkp = t & 7;    // 0..7
    const float* vptr = values + (size_t)(row0 + lr) * Dc + lkp * 2;
    float* vsf = (float*)Vs4;
    const int vsi = ((lr >> 1) * 8 + lkp) * 4;
    const int vlo = lr & 1;

#pragma unroll 1
    for (int kt = 0; kt < Dc / KT; kt++) {
        // --- load W2 tile (2048 float4, coalesced) ---
        const float4* wsrc = (const float4*)(W2 + (size_t)kt * KT * Uc);
        float4* wdst = (float4*)W2s;
#pragma unroll
        for (int i = 0; i < 4; i++) wdst[t + i * 512] = wsrc[t + i * 512];
        // --- load values tile (row-pair interleaved for f32x2) ---
        float2 f2 = *(const float2*)(vptr + kt * KT);
        vsf[vsi + vlo]     = f2.x;
        vsf[vsi + 2 + vlo] = f2.y;
        __syncthreads();

#pragma unroll
        for (int kp = 0; kp < 8; kp++) {
            const float w0 = W2s[2 * kp][t];
            const float w1 = W2s[2 * kp + 1][t];
            unsigned long long w20, w21;
            asm("mov.b64 %0, {%1, %1};" : "=l"(w20) : "f"(w0));
            asm("mov.b64 %0, {%1, %1};" : "=l"(w21) : "f"(w1));
            const unsigned abase = vs_base + kp * 16;
            sfor<32>([&](auto jc) {
                constexpr int j = decltype(jc)::v;
                unsigned long long va, vb;
                asm volatile("ld.shared.b64 %0, [%1+%2];"
                             : "=l"(va) : "r"(abase), "n"(j * 128));
                asm volatile("ld.shared.b64 %0, [%1+%2];"
                             : "=l"(vb) : "r"(abase), "n"(j * 128 + 8));
                asm("fma.rn.f32x2 %0, %1, %2, %0;" : "+l"(acc[j]) : "l"(va), "l"(w20));
                asm("fma.rn.f32x2 %0, %1, %2, %0;" : "+l"(acc[j]) : "l"(vb), "l"(w21));
            });
        }
        __syncthreads();
    }

    // --- epilogue: h = tanh(qp + mv), score = sum_u V[u]*h[u] ---
    const float Vt  = Vw[t];
    const float qpv = g_qp[b * Uc + t];
    const int lane = t & 31, wrp = t >> 5;
#pragma unroll
    for (int j = 0; j < 32; j++) {
        float m0, m1;
        asm("mov.b64 {%0, %1}, %2;" : "=f"(m0), "=f"(m1) : "l"(acc[j]));
        float c0 = Vt * tanhf(qpv + m0);
        float c1 = Vt * tanhf(qpv + m1);
#pragma unroll
        for (int o = 16; o; o >>= 1) {
            c0 += __shfl_xor_sync(0xffffffffu, c0, o);
            c1 += __shfl_xor_sync(0xffffffffu, c1, o);
        }
        if (lane == 0) { red[2 * j][wrp] = c0; red[2 * j + 1][wrp] = c1; }
    }
    __syncthreads();
    if (t < TSR) {
        float s = 0.f;
#pragma unroll
        for (int w = 0; w < 16; w++) s += red[t][w];
        g_scores[row0 + t] = s;   // bv dropped: softmax shift-invariant
    }
}

// ---------------------------------------------------------------------------
// Kernel C1: per-batch softmax stats (max, 1/sum)
// ---------------------------------------------------------------------------
__global__ void softmax_stats_kernel() {
    __shared__ float sh[Sc];
    __shared__ float r32[32];
    const int b = blockIdx.x, t = threadIdx.x;  // 512 threads
    const int lane = t & 31, wrp = t >> 5;

    float lmax = -1e30f;
#pragma unroll
    for (int i = 0; i < 4; i++) {
        float v = g_scores[b * Sc + t + i * 512];
        sh[t + i * 512] = v;
        lmax = fmaxf(lmax, v);
    }
#pragma unroll
    for (int o = 16; o; o >>= 1) lmax = fmaxf(lmax, __shfl_xor_sync(0xffffffffu, lmax, o));
    if (lane == 0) r32[wrp] = lmax;
    __syncthreads();
    if (t < 32) {
        float v = (t < 16) ? r32[t] : -1e30f;
#pragma unroll
        for (int o = 8; o; o >>= 1) v = fmaxf(v, __shfl_xor_sync(0xffffffffu, v, o));
        if (t == 0) r32[16] = v;
    }
    __syncthreads();
    const float mx = r32[16];

    float ls = 0.f;
#pragma unroll
    for (int i = 0; i < 4; i++) ls += expf(sh[t + i * 512] - mx);
#pragma unroll
    for (int o = 16; o; o >>= 1) ls += __shfl_xor_sync(0xffffffffu, ls, o);
    __syncthreads();
    if (lane == 0) r32[wrp] = ls;
    __syncthreads();
    if (t == 0) {
        float s = 0.f;
        for (int i = 0; i < 16; i++) s += r32[i];
        g_max[b] = mx;
        g_rsum[b] = 1.f / s;
    }
}

// ---------------------------------------------------------------------------
// Kernel C2: partial context over an S-chunk (8 chunks per batch)
// ---------------------------------------------------------------------------
__global__ void context_partial_kernel(const float* __restrict__ values) {
    __shared__ float ws[Sc / NCH];  // 256 weights
    const int ch = blockIdx.x, b = blockIdx.y, t = threadIdx.x;  // 512 threads
    const float mx = g_max[b], rs = g_rsum[b];
    if (t < Sc / NCH)
        ws[t] = expf(g_scores[b * Sc + ch * (Sc / NCH) + t] - mx) * rs;
    __syncthreads();

    const float* vp = values + (size_t)(b * Sc + ch * (Sc / NCH)) * Dc + t;
    float acc = 0.f;
#pragma unroll 8
    for (int i = 0; i < Sc / NCH; i++)
        acc = fmaf(ws[i], vp[(size_t)i * Dc], acc);
    g_part[(b * NCH + ch) * Dc + t] = acc;
}

// ---------------------------------------------------------------------------
// Kernel C3: reduce 8 partials -> context output [B, D]
// ---------------------------------------------------------------------------
__global__ void context_reduce_kernel(float* __restrict__ out) {
    const int b = blockIdx.x, t = threadIdx.x;
    float s = 0.f;
#pragma unroll
    for (int ch = 0; ch < NCH; ch++)
        s += g_part[(b * NCH + ch) * Dc + t];
    out[b * Dc + t] = s;
}

// ---------------------------------------------------------------------------
extern "C" void kernel_launch(void* const* d_in, const int* in_sizes, int n_in,
                              void* d_out, int out_size) {
    (void)in_sizes; (void)n_in; (void)out_size;
    const float* query  = (const float*)d_in[0];
    const float* values = (const float*)d_in[1];
    const float* W1     = (const float*)d_in[2];
    const float* b1     = (const float*)d_in[3];
    const float* W2     = (const float*)d_in[4];
    const float* b2     = (const float*)d_in[5];
    const float* Vw     = (const float*)d_in[6];
    // d_in[7] = bv: softmax over S is invariant to a constant shift -> unused
    float* out = (float*)d_out;

    qproj_kernel<<<Bc, Uc>>>(query, W1, b1, b2);
    score_kernel<<<(Bc * Sc) / TSR, 512>>>(values, W2, Vw);
    softmax_stats_kernel<<<Bc, 512>>>();
    context_partial_kernel<<<dim3(NCH, Bc), 512>>>(values);
    context_reduce_kernel<<<Bc, Dc>>>(out);
}

// round 8
// speedup vs baseline: 1.0004x; 1.0004x over previous
#include <cuda_runtime.h>

// Problem constants
#define Bc 64
#define Sc 2048
#define Dc 512
#define Uc 512
#define TSR 64     // rows per score block
#define KT  16     // K tile
#define NCH 8      // context S-chunks per batch

// Scratch (no allocations allowed)
__device__ float g_qp[Bc * Uc];        // q_proj + b1 + b2
__device__ float g_scores[Bc * Sc];    // raw scores
__device__ float g_max[Bc];
__device__ float g_rsum[Bc];
__device__ float g_part[Bc * NCH * Dc];

// compile-time unroller (constexpr index for "n" asm constraints)
template <int J> struct IC { static constexpr int v = J; };
template <int N, class F>
__device__ __forceinline__ void sfor(F&& f) {
    if constexpr (N > 0) { sfor<N - 1>(f); f(IC<N - 1>{}); }
}

// ---------------------------------------------------------------------------
// Kernel A: q_proj[b][u] = query[b]@W1[:,u] + b1[u] + b2[u]
// ---------------------------------------------------------------------------
__global__ void qproj_kernel(const float* __restrict__ query,
                             const float* __restrict__ W1,
                             const float* __restrict__ b1,
                             const float* __restrict__ b2) {
    __shared__ float q[Dc];
    const int b = blockIdx.x, t = threadIdx.x;
    q[t] = query[b * Dc + t];
    __syncthreads();
    float acc = b1[t] + b2[t];
#pragma unroll 8
    for (int d = 0; d < Dc; d++)
        acc = fmaf(q[d], W1[d * Uc + t], acc);
    g_qp[b * Uc + t] = acc;
}

// ---------------------------------------------------------------------------
// Kernel B: fused  scores[row] = V . tanh(q_proj[b] + values[row]@W2)
// Block: 64 rows x 512 cols, 512 threads, f32x2-packed accumulators.
// ---------------------------------------------------------------------------
__global__ void __launch_bounds__(512, 1)
score_kernel(const float* __restrict__ values,
             const float* __restrict__ W2,
             const float* __restrict__ Vw) {
    __shared__ float  W2s[KT][Uc];          // 32 KB: W2[k0+kk][c]
    __shared__ float4 Vs4[TSR / 2][KT / 2]; // 4 KB: {v(2j,k0),v(2j+1,k0),v(2j,k1),v(2j+1,k1)}
    __shared__ float  red[TSR][17];         // reduction scratch

    const int t = threadIdx.x;
    const int row0 = blockIdx.x * TSR;   // global row in [0, B*S)
    const int b = row0 >> 11;            // row0 / Sc (TSR divides Sc)

    unsigned long long acc[32];
#pragma unroll
    for (int j = 0; j < 32; j++) acc[j] = 0ULL;

    const unsigned vs_base = (unsigned)__cvta_generic_to_shared(Vs4);

    // values-tile loader mapping: thread -> (row lr, k-pair lkp), float2 per thread
    const int lr  = t >> 3;   // 0..63
    const int lkp = t & 7;    // 0..7
    const float* vptr = values + (size_t)(row0 + lr) * Dc + lkp * 2;
    float* vsf = (float*)Vs4;
    const int vsi = ((lr >> 1) * 8 + lkp) * 4;
    const int vlo = lr & 1;

#pragma unroll 1
    for (int kt = 0; kt < Dc / KT; kt++) {
        // --- load W2 tile (2048 float4, coalesced) ---
        const float4* wsrc = (const float4*)(W2 + (size_t)kt * KT * Uc);
        float4* wdst = (float4*)W2s;
#pragma unroll
        for (int i = 0; i < 4; i++) wdst[t + i * 512] = wsrc[t + i * 512];
        // --- load values tile (row-pair interleaved for f32x2) ---
        float2 f2 = *(const float2*)(vptr + kt * KT);
        vsf[vsi + vlo]     = f2.x;
        vsf[vsi + 2 + vlo] = f2.y;
        __syncthreads();

#pragma unroll
        for (int kp = 0; kp < 8; kp++) {
            const float w0 = W2s[2 * kp][t];
            const float w1 = W2s[2 * kp + 1][t];
            unsigned long long w20, w21;
            asm("mov.b64 %0, {%1, %1};" : "=l"(w20) : "f"(w0));
            asm("mov.b64 %0, {%1, %1};" : "=l"(w21) : "f"(w1));
            const unsigned abase = vs_base + kp * 16;
            sfor<32>([&](auto jc) {
                constexpr int j = decltype(jc)::v;
                unsigned long long va, vb;
                asm volatile("ld.shared.b64 %0, [%1+%2];"
                             : "=l"(va) : "r"(abase), "n"(j * 128));
                asm volatile("ld.shared.b64 %0, [%1+%2];"
                             : "=l"(vb) : "r"(abase), "n"(j * 128 + 8));
                asm("fma.rn.f32x2 %0, %1, %2, %0;" : "+l"(acc[j]) : "l"(va), "l"(w20));
                asm("fma.rn.f32x2 %0, %1, %2, %0;" : "+l"(acc[j]) : "l"(vb), "l"(w21));
            });
        }
        __syncthreads();
    }

    // --- epilogue: h = tanh(qp + mv), score = sum_u V[u]*h[u] ---
    const float Vt  = Vw[t];
    const float qpv = g_qp[b * Uc + t];
    const int lane = t & 31, wrp = t >> 5;
#pragma unroll
    for (int j = 0; j < 32; j++) {
        float m0, m1;
        asm("mov.b64 {%0, %1}, %2;" : "=f"(m0), "=f"(m1) : "l"(acc[j]));
        float c0 = Vt * tanhf(qpv + m0);
        float c1 = Vt * tanhf(qpv + m1);
#pragma unroll
        for (int o = 16; o; o >>= 1) {
            c0 += __shfl_xor_sync(0xffffffffu, c0, o);
            c1 += __shfl_xor_sync(0xffffffffu, c1, o);
        }
        if (lane == 0) { red[2 * j][wrp] = c0; red[2 * j + 1][wrp] = c1; }
    }
    __syncthreads();
    if (t < TSR) {
        float s = 0.f;
#pragma unroll
        for (int w = 0; w < 16; w++) s += red[t][w];
        g_scores[row0 + t] = s;   // bv dropped: softmax shift-invariant
    }
}

// ---------------------------------------------------------------------------
// Kernel C1: per-batch softmax stats (max, 1/sum)
// ---------------------------------------------------------------------------
__global__ void softmax_stats_kernel() {
    __shared__ float sh[Sc];
    __shared__ float r32[32];
    const int b = blockIdx.x, t = threadIdx.x;  // 512 threads
    const int lane = t & 31, wrp = t >> 5;

    float lmax = -1e30f;
#pragma unroll
    for (int i = 0; i < 4; i++) {
        float v = g_scores[b * Sc + t + i * 512];
        sh[t + i * 512] = v;
        lmax = fmaxf(lmax, v);
    }
#pragma unroll
    for (int o = 16; o; o >>= 1) lmax = fmaxf(lmax, __shfl_xor_sync(0xffffffffu, lmax, o));
    if (lane == 0) r32[wrp] = lmax;
    __syncthreads();
    if (t < 32) {
        float v = (t < 16) ? r32[t] : -1e30f;
#pragma unroll
        for (int o = 8; o; o >>= 1) v = fmaxf(v, __shfl_xor_sync(0xffffffffu, v, o));
        if (t == 0) r32[16] = v;
    }
    __syncthreads();
    const float mx = r32[16];

    float ls = 0.f;
#pragma unroll
    for (int i = 0; i < 4; i++) ls += expf(sh[t + i * 512] - mx);
#pragma unroll
    for (int o = 16; o; o >>= 1) ls += __shfl_xor_sync(0xffffffffu, ls, o);
    __syncthreads();
    if (lane == 0) r32[wrp] = ls;
    __syncthreads();
    if (t == 0) {
        float s = 0.f;
        for (int i = 0; i < 16; i++) s += r32[i];
        g_max[b] = mx;
        g_rsum[b] = 1.f / s;
    }
}

// ---------------------------------------------------------------------------
// Kernel C2: partial context over an S-chunk (8 chunks per batch)
// ---------------------------------------------------------------------------
__global__ void context_partial_kernel(const float* __restrict__ values) {
    __shared__ float ws[Sc / NCH];  // 256 weights
    const int ch = blockIdx.x, b = blockIdx.y, t = threadIdx.x;  // 512 threads
    const float mx = g_max[b], rs = g_rsum[b];
    if (t < Sc / NCH)
        ws[t] = expf(g_scores[b * Sc + ch * (Sc / NCH) + t] - mx) * rs;
    __syncthreads();

    const float* vp = values + (size_t)(b * Sc + ch * (Sc / NCH)) * Dc + t;
    float acc = 0.f;
#pragma unroll 8
    for (int i = 0; i < Sc / NCH; i++)
        acc = fmaf(ws[i], vp[(size_t)i * Dc], acc);
    g_part[(b * NCH + ch) * Dc + t] = acc;
}

// ---------------------------------------------------------------------------
// Kernel C3: reduce 8 partials -> context output [B, D]
// ---------------------------------------------------------------------------
__global__ void context_reduce_kernel(float* __restrict__ out) {
    const int b = blockIdx.x, t = threadIdx.x;
    float s = 0.f;
#pragma unroll
    for (int ch = 0; ch < NCH; ch++)
        s += g_part[(b * NCH + ch) * Dc + t];
    out[b * Dc + t] = s;
}

// ---------------------------------------------------------------------------
extern "C" void kernel_launch(void* const* d_in, const int* in_sizes, int n_in,
                              void* d_out, int out_size) {
    (void)in_sizes; (void)n_in; (void)out_size;
    const float* query  = (const float*)d_in[0];
    const float* values = (const float*)d_in[1];
    const float* W1     = (const float*)d_in[2];
    const float* b1     = (const float*)d_in[3];
    const float* W2     = (const float*)d_in[4];
    const float* b2     = (const float*)d_in[5];
    const float* Vw     = (const float*)d_in[6];
    // d_in[7] = bv: softmax over S is invariant to a constant shift -> unused
    float* out = (float*)d_out;

    qproj_kernel<<<Bc, Uc>>>(query, W1, b1, b2);
    score_kernel<<<(Bc * Sc) / TSR, 512>>>(values, W2, Vw);
    softmax_stats_kernel<<<Bc, 512>>>();
    context_partial_kernel<<<dim3(NCH, Bc), 512>>>(values);
    context_reduce_kernel<<<Bc, Dc>>>(out);
}

// round 9
// speedup vs baseline: 1.6021x; 1.6014x over previous
#include <cuda_runtime.h>

// Problem constants
#define Bc 64
#define Sc 2048
#define Dc 512
#define Uc 512
#define TSR 64     // rows per score block
#define KT  16     // K tile
#define NCH 16     // context S-chunks per batch

// Scratch (no allocations allowed)
__device__ float g_qp[Bc * Uc];        // q_proj + b1 + b2
__device__ float g_scores[Bc * Sc];    // raw scores
__device__ float g_max[Bc];
__device__ float g_rsum[Bc];
__device__ float g_part[Bc * NCH * Dc];

// ---------------------------------------------------------------------------
// Kernel A: q_proj[b][u] = query[b]@W1[:,u] + b1[u] + b2[u]
// ---------------------------------------------------------------------------
__global__ void qproj_kernel(const float* __restrict__ query,
                             const float* __restrict__ W1,
                             const float* __restrict__ b1,
                             const float* __restrict__ b2) {
    __shared__ float q[Dc];
    const int b = blockIdx.x, t = threadIdx.x;
    q[t] = query[b * Dc + t];
    __syncthreads();
    float acc = b1[t] + b2[t];
#pragma unroll 8
    for (int d = 0; d < Dc; d++)
        acc = fmaf(q[d], W1[d * Uc + t], acc);
    g_qp[b * Uc + t] = acc;
}

// ---------------------------------------------------------------------------
// Kernel B: fused  scores[row] = V . tanh(q_proj[b] + values[row]@W2)
// Block: 64 rows x 512 cols, 512 threads.
// Thread t: row-half ch = t>>8 (32 rows), cols {t&255, (t&255)+256}.
// f32x2-packed accumulators: 16 row-pairs x 2 cols.
// Each LDS.64 of a values row-pair feeds 2 FFMA2 (both columns).
// ---------------------------------------------------------------------------
__global__ void __launch_bounds__(512, 1)
score_kernel(const float* __restrict__ values,
             const float* __restrict__ W2,
             const float* __restrict__ Vw) {
    __shared__ float W2s[KT][Uc];                        // 32 KB
    __shared__ unsigned long long Vs2[TSR / 2][KT];      // 4 KB: {row 2r, row 2r+1} at k
    __shared__ float red[TSR][9];                        // per-row partials

    const int t = threadIdx.x;
    const int row0 = blockIdx.x * TSR;   // global row in [0, B*S)
    const int b = row0 >> 11;            // row0 / Sc
    const int ch = t >> 8;               // row half (0/1)
    const int c0 = t & 255;
    const int c1 = c0 + 256;

    unsigned long long acc[16][2];
#pragma unroll
    for (int rp = 0; rp < 16; rp++) { acc[rp][0] = 0ULL; acc[rp][1] = 0ULL; }

    // --- tile loader mappings ---
    // W2 tile: 2048 float4, thread loads 4 (coalesced)
    // values tile: thread reads float2 at (row vr = t>>3, k = (t&7)*2)
    const int vr = t >> 3;
    const int vk = (t & 7) * 2;
    const float* vptr = values + (size_t)(row0 + vr) * Dc + vk;
    float* vsf = (float*)Vs2;
    const int vsi = ((vr >> 1) * KT + vk) * 2 + (vr & 1);  // float index of f2.x slot
    // f2.y goes at k+1: index += 2

    const unsigned long long* vrow = &Vs2[ch * 16][0];

    // preload tile 0 into registers
    float4 wreg[4];
    float2 vreg;
    {
        const float4* wsrc = (const float4*)W2;
#pragma unroll
        for (int i = 0; i < 4; i++) wreg[i] = wsrc[t + i * 512];
        vreg = *(const float2*)vptr;
    }

#pragma unroll 1
    for (int kt = 0; kt < Dc / KT; kt++) {
        // stage registers -> shared
        {
            float4* wdst = (float4*)W2s;
#pragma unroll
            for (int i = 0; i < 4; i++) wdst[t + i * 512] = wreg[i];
            vsf[vsi]     = vreg.x;
            vsf[vsi + 2] = vreg.y;
        }
        __syncthreads();

        // prefetch next tile into registers (latency hidden under compute)
        if (kt != Dc / KT - 1) {
            const float4* wsrc = (const float4*)(W2 + (size_t)(kt + 1) * KT * Uc);
#pragma unroll
            for (int i = 0; i < 4; i++) wreg[i] = wsrc[t + i * 512];
            vreg = *(const float2*)(vptr + (kt + 1) * KT);
        }

        // compute
#pragma unroll
        for (int kp = 0; kp < 8; kp++) {
            const float w00f = W2s[2 * kp][c0];
            const float w10f = W2s[2 * kp + 1][c0];
            const float w01f = W2s[2 * kp][c1];
            const float w11f = W2s[2 * kp + 1][c1];
            unsigned long long w00, w10, w01, w11;
            asm("mov.b64 %0, {%1, %1};" : "=l"(w00) : "f"(w00f));
            asm("mov.b64 %0, {%1, %1};" : "=l"(w10) : "f"(w10f));
            asm("mov.b64 %0, {%1, %1};" : "=l"(w01) : "f"(w01f));
            asm("mov.b64 %0, {%1, %1};" : "=l"(w11) : "f"(w11f));
#pragma unroll
            for (int rp = 0; rp < 16; rp++) {
                const unsigned long long va = vrow[rp * KT + 2 * kp];
                const unsigned long long vb = vrow[rp * KT + 2 * kp + 1];
                asm("fma.rn.f32x2 %0, %1, %2, %0;" : "+l"(acc[rp][0]) : "l"(va), "l"(w00));
                asm("fma.rn.f32x2 %0, %1, %2, %0;" : "+l"(acc[rp][1]) : "l"(va), "l"(w01));
                asm("fma.rn.f32x2 %0, %1, %2, %0;" : "+l"(acc[rp][0]) : "l"(vb), "l"(w10));
                asm("fma.rn.f32x2 %0, %1, %2, %0;" : "+l"(acc[rp][1]) : "l"(vb), "l"(w11));
            }
        }
        __syncthreads();
    }

    // --- epilogue: h = tanh(qp + mv), score = sum_u V[u]*h[u] ---
    const float V0 = Vw[c0], V1 = Vw[c1];
    const float qp0 = g_qp[b * Uc + c0], qp1 = g_qp[b * Uc + c1];
    const int lane = t & 31, wrp = t >> 5;  // wrp 0..15; (wrp&7) is slot within half
#pragma unroll
    for (int rp = 0; rp < 16; rp++) {
        float m00, m01, m10, m11;
        asm("mov.b64 {%0, %1}, %2;" : "=f"(m00), "=f"(m01) : "l"(acc[rp][0]));
        asm("mov.b64 {%0, %1}, %2;" : "=f"(m10), "=f"(m11) : "l"(acc[rp][1]));
        float se = V0 * tanhf(qp0 + m00) + V1 * tanhf(qp1 + m10);  // even row
        float so = V0 * tanhf(qp0 + m01) + V1 * tanhf(qp1 + m11);  // odd row
#pragma unroll
        for (int o = 16; o; o >>= 1) {
            se += __shfl_xor_sync(0xffffffffu, se, o);
            so += __shfl_xor_sync(0xffffffffu, so, o);
        }
        if (lane == 0) {
            const int r = ch * 32 + 2 * rp;
            red[r][wrp & 7]     = se;
            red[r + 1][wrp & 7] = so;
        }
    }
    __syncthreads();
    if (t < TSR) {
        float s = 0.f;
#pragma unroll
        for (int w = 0; w < 8; w++) s += red[t][w];
        g_scores[row0 + t] = s;   // bv dropped: softmax shift-invariant
    }
}

// ---------------------------------------------------------------------------
// Kernel C1: per-batch softmax stats (max, 1/sum)
// ---------------------------------------------------------------------------
__global__ void softmax_stats_kernel() {
    __shared__ float sh[Sc];
    __shared__ float r32[32];
    const int b = blockIdx.x, t = threadIdx.x;  // 512 threads
    const int lane = t & 31, wrp = t >> 5;

    float lmax = -1e30f;
#pragma unroll
    for (int i = 0; i < 4; i++) {
        float v = g_scores[b * Sc + t + i * 512];
        sh[t + i * 512] = v;
        lmax = fmaxf(lmax, v);
    }
#pragma unroll
    for (int o = 16; o; o >>= 1) lmax = fmaxf(lmax, __shfl_xor_sync(0xffffffffu, lmax, o));
    if (lane == 0) r32[wrp] = lmax;
    __syncthreads();
    if (t < 32) {
        float v = (t < 16) ? r32[t] : -1e30f;
#pragma unroll
        for (int o = 8; o; o >>= 1) v = fmaxf(v, __shfl_xor_sync(0xffffffffu, v, o));
        if (t == 0) r32[16] = v;
    }
    __syncthreads();
    const float mx = r32[16];

    float ls = 0.f;
#pragma unroll
    for (int i = 0; i < 4; i++) ls += expf(sh[t + i * 512] - mx);
#pragma unroll
    for (int o = 16; o; o >>= 1) ls += __shfl_xor_sync(0xffffffffu, ls, o);
    __syncthreads();
    if (lane == 0) r32[wrp] = ls;
    __syncthreads();
    if (t == 0) {
        float s = 0.f;
        for (int i = 0; i < 16; i++) s += r32[i];
        g_max[b] = mx;
        g_rsum[b] = 1.f / s;
    }
}

// ---------------------------------------------------------------------------
// Kernel C2: partial context over an S-chunk (NCH chunks per batch)
// ---------------------------------------------------------------------------
__global__ void context_partial_kernel(const float* __restrict__ values) {
    __shared__ float ws[Sc / NCH];  // 128 weights
    const int ch = blockIdx.x, b = blockIdx.y, t = threadIdx.x;  // 512 threads
    const float mx = g_max[b], rs = g_rsum[b];
    if (t < Sc / NCH)
        ws[t] = expf(g_scores[b * Sc + ch * (Sc / NCH) + t] - mx) * rs;
    __syncthreads();

    const float* vp = values + (size_t)(b * Sc + ch * (Sc / NCH)) * Dc + t;
    float acc = 0.f;
#pragma unroll 16
    for (int i = 0; i < Sc / NCH; i++)
        acc = fmaf(ws[i], vp[(size_t)i * Dc], acc);
    g_part[(b * NCH + ch) * Dc + t] = acc;
}

// ---------------------------------------------------------------------------
// Kernel C3: reduce NCH partials -> context output [B, D]
// ---------------------------------------------------------------------------
__global__ void context_reduce_kernel(float* __restrict__ out) {
    const int b = blockIdx.x, t = threadIdx.x;
    float s = 0.f;
#pragma unroll
    for (int ch = 0; ch < NCH; ch++)
        s += g_part[(b * NCH + ch) * Dc + t];
    out[b * Dc + t] = s;
}

// ---------------------------------------------------------------------------
extern "C" void kernel_launch(void* const* d_in, const int* in_sizes, int n_in,
                              void* d_out, int out_size) {
    (void)in_sizes; (void)n_in; (void)out_size;
    const float* query  = (const float*)d_in[0];
    const float* values = (const float*)d_in[1];
    const float* W1     = (const float*)d_in[2];
    const float* b1     = (const float*)d_in[3];
    const float* W2     = (const float*)d_in[4];
    const float* b2     = (const float*)d_in[5];
    const float* Vw     = (const float*)d_in[6];
    // d_in[7] = bv: softmax over S is invariant to a constant shift -> unused
    float* out = (float*)d_out;

    qproj_kernel<<<Bc, Uc>>>(query, W1, b1, b2);
    score_kernel<<<(Bc * Sc) / TSR, 512>>>(values, W2, Vw);
    softmax_stats_kernel<<<Bc, 512>>>();
    context_partial_kernel<<<dim3(NCH, Bc), 512>>>(values);
    context_reduce_kernel<<<Bc, Dc>>>(out);
}